// round 17
// baseline (speedup 1.0000x reference)
#include <cuda_runtime.h>
#include <cuda_fp16.h>
#include <cstdint>

#define NL 4
#define TT 64
#define WARPS 8
#define THREADS (WARPS * 32)        // 256: each warp owns 16 rows end-to-end
#define ROWS_CTA (WARPS * 16)       // 128
#define BTOT 16384

// SMEM: weights 64KB + bias 1KB
#define OFF_BIAS 65536u
#define DSMEM    (65536 + 1024 + 64)

// staged data (built by prep_kernel)
__device__ uint32_t gBF[16384];      // fp16 W fragment PAIRS [l][kc][ntp][lane][w4] (64KB)
__device__ uint32_t gBias2[256];     // prescaled half2 bias quads [l][jtc][q][g4] (1KB)
__device__ float    gWl[32];
__device__ float    gBl;

// ---------------- helpers ----------------
__device__ __forceinline__ uint32_t smem_u32(const void* p) {
    uint32_t a;
    asm("{ .reg .u64 t; cvta.to.shared.u64 t, %1; cvt.u32.u64 %0, t; }" : "=r"(a) : "l"(p));
    return a;
}
__device__ __forceinline__ void mma16816(float d[4], const uint32_t a[4], uint32_t b0, uint32_t b1) {
    asm volatile("mma.sync.aligned.m16n8k16.row.col.f32.f16.f16.f32 "
                 "{%0,%1,%2,%3}, {%4,%5,%6,%7}, {%8,%9}, {%0,%1,%2,%3};"
                 : "+f"(d[0]), "+f"(d[1]), "+f"(d[2]), "+f"(d[3])
                 : "r"(a[0]), "r"(a[1]), "r"(a[2]), "r"(a[3]), "r"(b0), "r"(b1));
}
__device__ __forceinline__ void ldf4(uint32_t* f, uint32_t addr) {
    asm volatile("ld.shared.v4.u32 {%0,%1,%2,%3}, [%4];"
                 : "=r"(f[0]), "=r"(f[1]), "=r"(f[2]), "=r"(f[3]) : "r"(addr));
}
__device__ __forceinline__ uint32_t pk2h(float a, float b) {
    __half2 t = __floats2half2_rn(a, b);
    return *(uint32_t*)&t;
}
__device__ __forceinline__ uint32_t tanh2(uint32_t v) {
    uint32_t r; asm("tanh.approx.f16x2 %0, %1;" : "=r"(r) : "r"(v)); return r;
}
__device__ __forceinline__ float lo2f(uint32_t v) { return __low2float(*(__half2*)&v); }
__device__ __forceinline__ float hi2f(uint32_t v) { return __high2float(*(__half2*)&v); }
__device__ __forceinline__ uint32_t hmul2u(uint32_t a, uint32_t b) {
    __half2 r = __hmul2(*(__half2*)&a, *(__half2*)&b);
    return *(uint32_t*)&r;
}
__device__ __forceinline__ uint32_t hfma2u(uint32_t a, uint32_t b, uint32_t c) {
    __half2 r = __hfma2(*(__half2*)&a, *(__half2*)&b, *(__half2*)&c);
    return *(uint32_t*)&r;
}
__device__ __forceinline__ float sigm_ex(float v) {
    return __fdividef(1.f, 1.f + __expf(-v));
}

// ---------------- prep ----------------
__device__ __forceinline__ float getW(const float* W_ih0, const float* W_ih, const float* W_hh,
                                      int l, int n, int k) {
    if (k < 32) {
        if (l == 0) return (k < 2) ? W_ih0[n * 2 + k] : 0.f;
        return W_ih[(l - 1) * 4096 + n * 32 + k];
    }
    return W_hh[l * 4096 + n * 32 + (k - 32)];
}

__global__ void prep_kernel(const float* __restrict__ W_ih0, const float* __restrict__ W_ih,
                            const float* __restrict__ W_hh, const float* __restrict__ b_ih,
                            const float* __restrict__ b_hh, const float* __restrict__ W_lin,
                            const float* __restrict__ b_lin) {
    int i = blockIdx.x * blockDim.x + threadIdx.x;
    if (i < 16384) {
        // paired layout: w4 = i&3 -> (nt = 2*ntp + (w4>>1), word = w4&1)
        int w4 = i & 3, lane = (i >> 2) & 31, ntp = (i >> 7) & 7, kc = (i >> 10) & 3, l = i >> 12;
        int nt = ntp * 2 + (w4 >> 1), word = w4 & 1;
        int n  = nt * 8 + (lane >> 2);
        int k0 = kc * 16 + (lane & 3) * 2 + word * 8;
        float w0 = getW(W_ih0, W_ih, W_hh, l, n, k0);
        float w1 = getW(W_ih0, W_ih, W_hh, l, n, k0 + 1);
        gBF[i] = pk2h(w0, w1);
    }
    if (i < 256) {
        // bias quad layout: j = ((l*4 + jtc)*4 + q)*4 + g4
        int g4 = i & 3, q = (i >> 2) & 3, jtc = (i >> 4) & 3, l = i >> 6;
        int n = (g4 * 4 + jtc) * 8 + q * 2;
        float s = (g4 == 2) ? 1.0f : 0.5f;
        float b0 = b_ih[l * 128 + n]     + b_hh[l * 128 + n];
        float b1 = b_ih[l * 128 + n + 1] + b_hh[l * 128 + n + 1];
        gBias2[i] = pk2h(s * b0, s * b1);
    }
    if (i < 32) gWl[i] = W_lin[i];
    if (i == 0) gBl = b_lin[0];
}

// ---------------- main kernel ----------------
__global__ void __launch_bounds__(THREADS, 1)
lstm_kernel(const float* __restrict__ x, float* __restrict__ out) {
    extern __shared__ __align__(16) uint4 smemraw[];
    const uint32_t smB   = smem_u32(smemraw);
    const uint32_t biasB = smB + OFF_BIAS;

    const int tid  = threadIdx.x;
    const int w    = tid >> 5;
    const int lane = tid & 31;
    const int q    = lane & 3;
    const int r    = lane >> 2;
    const int gb0  = blockIdx.x * ROWS_CTA + w * 16;
    const uint32_t lane16 = (uint32_t)lane * 16u;

    // ---- stage weights + bias quads into SMEM ----
    {
        const uint4* src = (const uint4*)gBF;
        uint4* dst = (uint4*)smemraw;
        for (int i = tid; i < 4096; i += THREADS) dst[i] = src[i];
        if (tid < 64) ((uint4*)((char*)smemraw + OFF_BIAS))[tid] = ((const uint4*)gBias2)[tid];
    }
    __syncthreads();

    // h A-fragments per layer, register-resident (D->A identity, R7-validated)
    uint32_t hA[NL][2][4];
#pragma unroll
    for (int l = 0; l < NL; ++l)
#pragma unroll
        for (int ch = 0; ch < 2; ++ch)
#pragma unroll
            for (int rr = 0; rr < 4; ++rr) hA[l][ch][rr] = 0u;

    float cst[NL][4][4];
#pragma unroll
    for (int l = 0; l < NL; ++l)
#pragma unroll
        for (int jtc = 0; jtc < 4; ++jtc)
#pragma unroll
            for (int p = 0; p < 4; ++p) cst[l][jtc][p] = 0.f;

    const uint32_t h05 = pk2h(0.5f, 0.5f);
    const float* xq = x + (size_t)(gb0 + r) * 192;

#pragma unroll 1
    for (int t = 0; t < TT; ++t) {
        // ---- x fragment (layer 0, kc0): k=0,1 live in q==0 lanes ----
        uint32_t ax[4] = {0u, 0u, 0u, 0u};
        if (q == 0) {
            ax[0] = pk2h(__ldg(xq + t),        __ldg(xq + 64 + t));          // row r
            ax[1] = pk2h(__ldg(xq + 1536 + t), __ldg(xq + 1600 + t));        // row r+8
        }

#pragma unroll
        for (int l = 0; l < NL; ++l) {
            const uint32_t bL = smB + (uint32_t)l * 16384u + lane16;

            float d[16][4];
#pragma unroll
            for (int nt = 0; nt < 16; ++nt)
#pragma unroll
                for (int p = 0; p < 4; ++p) d[nt][p] = 0.f;

            // ---- MMAs: kc order {2,3,0,1}; h_prev first (independent of epilogue) ----
#pragma unroll
            for (int ki = 0; ki < 4; ++ki) {
                const int kc = (ki + 2) & 3;
                const uint32_t* A;
                if (kc < 2) {
                    if (l == 0) {
                        if (kc == 1) continue;       // l0: zero-padded ih cols 16..31
                        A = ax;
                    } else {
                        A = hA[l - 1][kc];           // h_in (just produced this step)
                    }
                } else {
                    A = hA[l][kc - 2];               // h_prev (from step t-1)
                }
#pragma unroll
                for (int ntp = 0; ntp < 8; ++ntp) {
                    uint32_t f[4];
                    ldf4(f, bL + (uint32_t)(kc * 4096 + ntp * 512));
                    mma16816(d[2 * ntp],     A, f[0], f[1]);
                    mma16816(d[2 * ntp + 1], A, f[2], f[3]);
                }
            }

            // ---- f16x2 epilogue; h goes straight back into A-fragments ----
#pragma unroll
            for (int jtc = 0; jtc < 4; ++jtc) {
                uint32_t bq[4];          // prescaled (bi, bf, bg, bo)
                ldf4(bq, biasB + (uint32_t)(((l * 4 + jtc) * 4 + q) * 16));
#pragma unroll
                for (int pr = 0; pr < 2; ++pr) {
                    const int p0 = pr * 2;
                    uint32_t ti = tanh2(hfma2u(pk2h(d[0 * 4 + jtc][p0], d[0 * 4 + jtc][p0 + 1]), h05, bq[0]));
                    uint32_t tf = tanh2(hfma2u(pk2h(d[1 * 4 + jtc][p0], d[1 * 4 + jtc][p0 + 1]), h05, bq[1]));
                    uint32_t tg = tanh2(hfma2u(pk2h(d[2 * 4 + jtc][p0], d[2 * 4 + jtc][p0 + 1]),
                                               pk2h(1.0f, 1.0f), bq[2]));
                    uint32_t to = tanh2(hfma2u(pk2h(d[3 * 4 + jtc][p0], d[3 * 4 + jtc][p0 + 1]), h05, bq[3]));
                    float i0 = fmaf(0.5f, lo2f(ti), 0.5f), i1 = fmaf(0.5f, hi2f(ti), 0.5f);
                    float f0 = fmaf(0.5f, lo2f(tf), 0.5f), f1 = fmaf(0.5f, hi2f(tf), 0.5f);
                    float g0 = lo2f(tg), g1 = hi2f(tg);
                    float c0 = fmaf(f0, cst[l][jtc][p0],     i0 * g0);
                    float c1 = fmaf(f1, cst[l][jtc][p0 + 1], i1 * g1);
                    cst[l][jtc][p0]     = c0;
                    cst[l][jtc][p0 + 1] = c1;
                    uint32_t tc = tanh2(pk2h(c0, c1));
                    uint32_t o2 = hfma2u(to, h05, h05);
                    hA[l][jtc >> 1][(jtc & 1) * 2 + pr] = hmul2u(o2, tc);
                }
            }
        }
    }

    // ---- head (warp-local): out = sigmoid(h3 . Wlin + b) ----
    float prow[2] = {0.f, 0.f};
#pragma unroll
    for (int ch = 0; ch < 2; ++ch)
#pragma unroll
        for (int rr = 0; rr < 4; ++rr) {
            int jtc = ch * 2 + (rr >> 1);
            int pr  = rr & 1;
            uint32_t h2 = hA[NL - 1][ch][rr];
            float w0 = __ldg(gWl + jtc * 8 + q * 2);
            float w1 = __ldg(gWl + jtc * 8 + q * 2 + 1);
            prow[pr] = fmaf(lo2f(h2), w0, prow[pr]);
            prow[pr] = fmaf(hi2f(h2), w1, prow[pr]);
        }
#pragma unroll
    for (int pr = 0; pr < 2; ++pr) {
        prow[pr] += __shfl_xor_sync(0xffffffffu, prow[pr], 1);
        prow[pr] += __shfl_xor_sync(0xffffffffu, prow[pr], 2);
    }
    if (q == 0) {
        float bl = gBl;
        out[gb0 + r]     = sigm_ex(prow[0] + bl);
        out[gb0 + r + 8] = sigm_ex(prow[1] + bl);
    }
}

extern "C" void kernel_launch(void* const* d_in, const int* in_sizes, int n_in,
                              void* d_out, int out_size) {
    const float* x     = (const float*)d_in[0];
    const float* W_ih0 = (const float*)d_in[1];
    const float* W_ih  = (const float*)d_in[2];
    const float* W_hh  = (const float*)d_in[3];
    const float* b_ih  = (const float*)d_in[4];
    const float* b_hh  = (const float*)d_in[5];
    const float* W_lin = (const float*)d_in[6];
    const float* b_lin = (const float*)d_in[7];

    prep_kernel<<<64, 256>>>(W_ih0, W_ih, W_hh, b_ih, b_hh, W_lin, b_lin);

    cudaFuncSetAttribute(lstm_kernel, cudaFuncAttributeMaxDynamicSharedMemorySize, DSMEM);

    int blocks = BTOT / ROWS_CTA;    // 128
    lstm_kernel<<<blocks, THREADS, DSMEM>>>(x, (float*)d_out);
}